// round 2
// baseline (speedup 1.0000x reference)
#include <cuda_runtime.h>
#include <cuda_bf16.h>

// CSR multi-head SpMM: out[n,h,d] = sum_{e in row n} ew[e,h] * nf[col[e],h,d]
// N=50000, E=800000, H=8, D=8  -> 64 floats per row.
// One warp per destination row. Lane L owns output elements 2L, 2L+1 (float2),
// which share head h = L>>2. Gather of a row of node_feat = one coalesced
// 256B warp read (all from L2 after warm-up since node_feat is 12.8MB).

#define H 8
#define D 8
#define ROW_ELEMS (H * D)

__global__ __launch_bounds__(256) void spmm_csr_kernel(
    const int* __restrict__ row_ptr,
    const int* __restrict__ col_idx,
    const float* __restrict__ edge_weight,   // [E, 8]
    const float* __restrict__ node_feat,     // [N, 64]
    float* __restrict__ out,                 // [N, 64]
    int n_nodes)
{
    int warp = (blockIdx.x * blockDim.x + threadIdx.x) >> 5;
    int lane = threadIdx.x & 31;
    if (warp >= n_nodes) return;

    int start = __ldg(&row_ptr[warp]);
    int end   = __ldg(&row_ptr[warp + 1]);

    int h = lane >> 2;                 // head index for this lane's pair
    float accx = 0.0f, accy = 0.0f;

    #pragma unroll 4
    for (int e = start; e < end; ++e) {
        int c   = __ldg(&col_idx[e]);
        float w = __ldg(&edge_weight[(size_t)e * H + h]);
        float2 f = *reinterpret_cast<const float2*>(
            node_feat + (size_t)c * ROW_ELEMS + lane * 2);
        accx = fmaf(w, f.x, accx);
        accy = fmaf(w, f.y, accy);
    }

    float2 r; r.x = accx; r.y = accy;
    *reinterpret_cast<float2*>(out + (size_t)warp * ROW_ELEMS + lane * 2) = r;
}

extern "C" void kernel_launch(void* const* d_in, const int* in_sizes, int n_in,
                              void* d_out, int out_size)
{
    const int*   row_ptr     = (const int*)d_in[0];
    const int*   col_idx     = (const int*)d_in[1];
    const float* edge_weight = (const float*)d_in[2];
    const float* node_feat   = (const float*)d_in[3];
    float*       out         = (float*)d_out;

    int n_nodes = in_sizes[0] - 1;          // row_ptr has N+1 entries

    const int threads = 256;                 // 8 warps / block
    int total_warps = n_nodes;
    int blocks = (total_warps * 32 + threads - 1) / threads;
    spmm_csr_kernel<<<blocks, threads>>>(row_ptr, col_idx, edge_weight,
                                         node_feat, out, n_nodes);
}